// round 17
// baseline (speedup 1.0000x reference)
#include <cuda_runtime.h>

#define MAXN 100000
#define MAXE 1600000
#define NEG 0.2f

typedef unsigned long long ull;

// ---------------- scratch (static device globals; no allocation) -------------
__device__ float g_h0 [MAXN * 16];    // relu(x@W0)
__device__ float g_hl [MAXN * 96];    // source transform (current layer)
__device__ float g_hr [MAXN * 96];    // target transform (current layer)
__device__ float g_acc[MAXN * 96];    // layer-1 accumulator = skip + b1 + msgs
__device__ int   g_src[MAXE];
__device__ int   g_dst[MAXE];
__device__ int   g_ssrc[MAXE];        // src ids sorted by dst (CSR payload)
__device__ int   g_cnt[MAXN];         // in-degree histogram
__device__ int   g_rs [MAXN + 1];     // CSR row starts
__device__ int   g_cur[MAXN];         // scatter cursors
__device__ int   g_bsum[128];
__device__ int   g_boff[128];
__device__ int   g_is64;

// ---------------- asm helpers -------------------------------------------------
__device__ __forceinline__ void ffma2(ull& acc, ull a, ull b) {
    asm("fma.rn.f32x2 %0, %1, %2, %0;" : "+l"(acc) : "l"(a), "l"(b));
}
__device__ __forceinline__ ull pack2(float x, float y) {
    ull r; asm("mov.b64 %0, {%1, %2};" : "=l"(r) : "f"(x), "f"(y)); return r;
}
__device__ __forceinline__ float2 unpack2(ull v) {
    float2 r; asm("mov.b64 {%0, %1}, %2;" : "=f"(r.x), "=f"(r.y) : "l"(v)); return r;
}
__device__ __forceinline__ float ex2(float v) {
    float r; asm("ex2.approx.ftz.f32 %0, %1;" : "=f"(r) : "f"(v)); return r;
}

// ---------------- init: zero histogram + dtype detect -------------------------
// Detect int64 vs int32 edge_index: node ids < 2^17, so int64 => odd words 0.
__global__ void k_init(const int* __restrict__ p, int n) {
    int i = blockIdx.x * blockDim.x + threadIdx.x;
    if (i < n) g_cnt[i] = 0;
    if (i == 0) {
        int acc = 0;
#pragma unroll
        for (int j = 1; j < 64; j += 2) acc |= p[j];
        g_is64 = (acc == 0) ? 1 : 0;
    }
}

__global__ void k_edges(const void* __restrict__ ei, int E) {
    int i = blockIdx.x * blockDim.x + threadIdx.x;
    if (i >= E) return;
    int s, d;
    if (g_is64) {
        const long long* p = (const long long*)ei;
        s = (int)p[i]; d = (int)p[E + i];
    } else {
        const int* p = (const int*)ei;
        s = p[i]; d = p[E + i];
    }
    g_src[i] = s;
    g_dst[i] = d;
    atomicAdd(&g_cnt[d], 1);
}

// ---------------- scan (3-kernel exclusive prefix sum over g_cnt) ------------

__global__ void k_scan1(int n) {
    __shared__ int tmp[1024];
    int tid = threadIdx.x;
    int i = blockIdx.x * 1024 + tid;
    int v = (i < n) ? g_cnt[i] : 0;
    tmp[tid] = v;
    __syncthreads();
#pragma unroll
    for (int o = 1; o < 1024; o <<= 1) {
        int t = (tid >= o) ? tmp[tid - o] : 0;
        __syncthreads();
        tmp[tid] += t;
        __syncthreads();
    }
    if (i < n) g_rs[i] = tmp[tid] - v;         // block-local exclusive
    if (tid == 1023) g_bsum[blockIdx.x] = tmp[tid];
}

__global__ void k_scan2(int nb) {
    __shared__ int tmp[128];
    int tid = threadIdx.x;
    int v = (tid < nb) ? g_bsum[tid] : 0;
    tmp[tid] = v;
    __syncthreads();
#pragma unroll
    for (int o = 1; o < 128; o <<= 1) {
        int t = (tid >= o) ? tmp[tid - o] : 0;
        __syncthreads();
        tmp[tid] += t;
        __syncthreads();
    }
    if (tid < nb) g_boff[tid] = tmp[tid] - v;  // exclusive block offsets
}

__global__ void k_scan3(int n, int E) {
    int i = blockIdx.x * blockDim.x + threadIdx.x;
    if (i < n) {
        int r = g_rs[i] + g_boff[i >> 10];
        g_rs[i] = r;
        g_cur[i] = r;
    }
    if (i == 0) g_rs[n] = E;
}

__global__ void k_scatter(int E) {
    int i = blockIdx.x * blockDim.x + threadIdx.x;
    if (i >= E) return;
    int d = g_dst[i];
    int pos = atomicAdd(&g_cur[d], 1);
    g_ssrc[pos] = g_src[i];
}

// ---------------- node transforms --------------------------------------------

// h0 = relu(x @ W0) : [n,128]@[128,16]. Shared-staged, float4 global loads.
__global__ void __launch_bounds__(256)
k_lin0(const float* __restrict__ x, const float* __restrict__ W0, int n) {
    __shared__ float sx[16 * 128];   // 16 rows of x
    __shared__ float sw[128 * 16];   // W0
    int tid = threadIdx.x;
    int row0 = blockIdx.x * 16;
    for (int i = tid; i < 512; i += 256)
        ((float4*)sw)[i] = ((const float4*)W0)[i];
    for (int i = tid; i < 512; i += 256) {
        int r = i >> 5;                // row within tile
        int row = row0 + r;
        float4 v = make_float4(0.f, 0.f, 0.f, 0.f);
        if (row < n) v = ((const float4*)x)[row * 32 + (i & 31)];
        ((float4*)sx)[i] = v;
    }
    __syncthreads();
    int r = tid >> 4, c = tid & 15;
    const float4* sxr = (const float4*)(sx + r * 128);
    float acc = 0.f;
#pragma unroll
    for (int k4 = 0; k4 < 32; k4++) {
        float4 h = sxr[k4];
        acc = fmaf(h.x, sw[(4 * k4 + 0) * 16 + c], acc);
        acc = fmaf(h.y, sw[(4 * k4 + 1) * 16 + c], acc);
        acc = fmaf(h.z, sw[(4 * k4 + 2) * 16 + c], acc);
        acc = fmaf(h.w, sw[(4 * k4 + 3) * 16 + c], acc);
    }
    int row = row0 + r;
    if (row < n) g_h0[row * 16 + c] = fmaxf(acc, 0.f);
}

// layer-1 transforms: weights in registers (one output column per thread),
// h rows staged in shared (broadcast reads). 64 rows per block.
__global__ void __launch_bounds__(384)
k_node1(const float* __restrict__ Wl, const float* __restrict__ bl,
        const float* __restrict__ Wr, const float* __restrict__ br,
        const float* __restrict__ Wf, const float* __restrict__ bf,
        const float* __restrict__ b1, int n) {
    __shared__ float sh[64 * 16];
    int c = threadIdx.x, ty = threadIdx.y;
    int tid = ty * 96 + c;
    int row0 = blockIdx.x * 64;
    float wl[16], wr[16], wf[16];
#pragma unroll
    for (int k = 0; k < 16; k++) {
        wl[k] = Wl[k * 96 + c];
        wr[k] = Wr[k * 96 + c];
        wf[k] = Wf[k * 96 + c];
    }
    float cbl = bl[c], cbr = br[c], cbf = bf[c] + b1[c];
    for (int i = tid; i < 1024; i += 384) {
        int r = i >> 4, k = i & 15;
        int row = row0 + r;
        sh[i] = (row < n) ? g_h0[row * 16 + k] : 0.f;
    }
    __syncthreads();
    for (int r = ty; r < 64; r += 4) {
        int row = row0 + r;
        if (row >= n) continue;
        float a0 = cbl, a1 = cbr, a2 = cbf;
#pragma unroll
        for (int k = 0; k < 16; k++) {
            float h = sh[r * 16 + k];
            a0 = fmaf(h, wl[k], a0);
            a1 = fmaf(h, wr[k], a1);
            a2 = fmaf(h, wf[k], a2);
        }
        g_hl[row * 96 + c] = a0;
        g_hr[row * 96 + c] = a1;
        g_acc[row * 96 + c] = a2;
    }
}

// layer-2 transforms v3. R15 analysis: previous versions were SMEM-CROSSBAR
// bound — each tile element was re-read by all 96 column-threads (2.4MB LDS
// traffic/block). New mapping: warp = ALL 96 columns (3 per lane), 8 rows per
// warp, ONE matrix at a time (tile reused from smem 3x). h-reads become
// warp-uniform broadcast LDS.128 (N=1, ~free); chunk weights live in 48 regs.
// Inner kk: 2 broadcast LDS.128 + 12 FFMA2 -> FFMA2-pipe bound (~83us floor).
__global__ void __launch_bounds__(256, 2)
k_node2(const float* __restrict__ Wl, const float* __restrict__ bl,
        const float* __restrict__ Wr, const float* __restrict__ br,
        const float* __restrict__ Wo, const float* __restrict__ bo,
        const float* __restrict__ b2, float* __restrict__ out, int n) {
    __shared__ float sh[96 * 68];      // 26112 B  tile [k][row], stride 68 (16B-aligned)
    __shared__ float swt[16 * 96];     // 6144 B   current chunk of current matrix
    int tid = threadIdx.x;
    int lane = tid & 31, wid = tid >> 5;   // 8 warps
    int row0 = blockIdx.x * 64;
    int c0 = lane, c1 = lane + 32, c2 = lane + 64;
    int rbase = wid * 8;                   // warp's 8 rows

    // load whole 64x96 tile, relu'd, transposed [k][row]
    for (int i = tid; i < 6144; i += 256) {
        int row = i / 96;
        int k = i - row * 96;
        int grow = row0 + row;
        float v = (grow < n) ? g_acc[grow * 96 + k] : 0.f;
        sh[k * 68 + row] = fmaxf(v, 0.f);
    }
    __syncthreads();

    for (int mat = 0; mat < 3; mat++) {
        const float* W = (mat == 0) ? Wl : ((mat == 1) ? Wr : Wo);
        float bb0, bb1, bb2;
        if (mat == 0)      { bb0 = bl[c0]; bb1 = bl[c1]; bb2 = bl[c2]; }
        else if (mat == 1) { bb0 = br[c0]; bb1 = br[c1]; bb2 = br[c2]; }
        else { bb0 = bo[c0] + b2[c0]; bb1 = bo[c1] + b2[c1]; bb2 = bo[c2] + b2[c2]; }

        ull a0[4], a1[4], a2[4];           // [row-pair p] per c-slot
#pragma unroll
        for (int p = 0; p < 4; p++) {
            a0[p] = pack2(bb0, bb0);
            a1[p] = pack2(bb1, bb1);
            a2[p] = pack2(bb2, bb2);
        }

        for (int ch = 0; ch < 6; ch++) {
            __syncthreads();               // all warps done with previous swt
            for (int i = tid; i < 1536; i += 256) swt[i] = W[ch * 1536 + i];
            __syncthreads();
            float w0[16], w1[16], w2[16];  // chunk weights in registers
#pragma unroll
            for (int kk = 0; kk < 16; kk++) {
                w0[kk] = swt[kk * 96 + c0];
                w1[kk] = swt[kk * 96 + c1];
                w2[kk] = swt[kk * 96 + c2];
            }
#pragma unroll
            for (int kk = 0; kk < 16; kk++) {
                const float* shk = sh + (ch * 16 + kk) * 68 + rbase;
                ull wp0 = pack2(w0[kk], w0[kk]);
                ull wp1 = pack2(w1[kk], w1[kk]);
                ull wp2 = pack2(w2[kk], w2[kk]);
#pragma unroll
                for (int q = 0; q < 2; q++) {
                    longlong2 h = *(const longlong2*)&shk[4 * q];  // broadcast
                    ull ha = (ull)h.x, hb = (ull)h.y;
                    ffma2(a0[2 * q], ha, wp0); ffma2(a0[2 * q + 1], hb, wp0);
                    ffma2(a1[2 * q], ha, wp1); ffma2(a1[2 * q + 1], hb, wp1);
                    ffma2(a2[2 * q], ha, wp2); ffma2(a2[2 * q + 1], hb, wp2);
                }
            }
        }

        float* dst = (mat == 0) ? g_hl : ((mat == 1) ? g_hr : out);
#pragma unroll
        for (int p = 0; p < 4; p++) {
            float2 v0 = unpack2(a0[p]);
            float2 v1 = unpack2(a1[p]);
            float2 v2 = unpack2(a2[p]);
            int ra = row0 + rbase + 2 * p, rb = ra + 1;
            if (ra < n) {
                dst[ra * 96 + c0] = v0.x; dst[ra * 96 + c1] = v1.x; dst[ra * 96 + c2] = v2.x;
            }
            if (rb < n) {
                dst[rb * 96 + c0] = v0.y; dst[rb * 96 + c1] = v1.y; dst[rb * 96 + c2] = v2.y;
            }
        }
    }
}

// ---------------- fused GATv2 edge phase: warp per node, 4 edges x 8 lanes ---
// SOFTWARE-PIPELINED: while batch b's shfl/ex2 chain runs, batch b+1's CSR
// index + 3 float4 h-rows are already in flight.
// mode: 0 = write ext_out, 1 = write g_acc (resolved in device code).
__global__ void __launch_bounds__(256, 3)
k_gat(const float* __restrict__ att, float* __restrict__ ext_out,
      int mode, int n) {
    int v = (blockIdx.x * blockDim.x + threadIdx.x) >> 5;
    int lane = threadIdx.x & 31;
    if (v >= n) return;
    float* out = (mode == 1) ? g_acc : ext_out;
    int grp = lane >> 3, g = lane & 7;
    int beg = g_rs[v], end = g_rs[v + 1];
    const float L2E = 1.44269504088896340736f;

    const float4* attv = (const float4*)att;
    float4 at0 = attv[g], at1 = attv[8 + g], at2 = attv[16 + g];
    at0.x *= L2E; at0.y *= L2E; at0.z *= L2E; at0.w *= L2E;
    at1.x *= L2E; at1.y *= L2E; at1.z *= L2E; at1.w *= L2E;
    at2.x *= L2E; at2.y *= L2E; at2.z *= L2E; at2.w *= L2E;

    const float4* hrv = (const float4*)(g_hr + (size_t)v * 96);
    float4 hr0 = hrv[g], hr1 = hrv[8 + g], hr2 = hrv[16 + g];

    float4 ac0 = make_float4(0.f, 0.f, 0.f, 0.f);
    float4 ac1 = ac0, ac2 = ac0;
    float den0 = 0.f, den1 = 0.f, den2 = 0.f;

    if (beg < end) {
        // prologue: load batch 0
        int e = beg + grp;
        int ee = (e < end) ? e : end - 1;
        int s = g_ssrc[ee];
        const float4* hlv = (const float4*)(g_hl + (size_t)s * 96);
        float4 h0 = hlv[g], h1 = hlv[8 + g], h2 = hlv[16 + g];

        for (int base = beg; base < end; base += 4) {
            float4 c0 = h0, c1 = h1, c2 = h2;
            bool cvalid = (base + grp) < end;
            int nbase = base + 4;
            if (nbase < end) {                 // prefetch batch b+1
                int e2 = nbase + grp;
                int ee2 = (e2 < end) ? e2 : end - 1;
                int s2 = g_ssrc[ee2];
                const float4* p = (const float4*)(g_hl + (size_t)s2 * 96);
                h0 = p[g]; h1 = p[8 + g]; h2 = p[16 + g];
            }

            float s0, s1, s2v, t;
            t = c0.x + hr0.x; t = fmaxf(t, NEG * t); s0 = at0.x * t;
            t = c0.y + hr0.y; t = fmaxf(t, NEG * t); s0 = fmaf(at0.y, t, s0);
            t = c0.z + hr0.z; t = fmaxf(t, NEG * t); s0 = fmaf(at0.z, t, s0);
            t = c0.w + hr0.w; t = fmaxf(t, NEG * t); s0 = fmaf(at0.w, t, s0);
            t = c1.x + hr1.x; t = fmaxf(t, NEG * t); s1 = at1.x * t;
            t = c1.y + hr1.y; t = fmaxf(t, NEG * t); s1 = fmaf(at1.y, t, s1);
            t = c1.z + hr1.z; t = fmaxf(t, NEG * t); s1 = fmaf(at1.z, t, s1);
            t = c1.w + hr1.w; t = fmaxf(t, NEG * t); s1 = fmaf(at1.w, t, s1);
            t = c2.x + hr2.x; t = fmaxf(t, NEG * t); s2v = at2.x * t;
            t = c2.y + hr2.y; t = fmaxf(t, NEG * t); s2v = fmaf(at2.y, t, s2v);
            t = c2.z + hr2.z; t = fmaxf(t, NEG * t); s2v = fmaf(at2.z, t, s2v);
            t = c2.w + hr2.w; t = fmaxf(t, NEG * t); s2v = fmaf(at2.w, t, s2v);

#pragma unroll
            for (int o = 4; o; o >>= 1) {       // reduce within 8-lane group
                s0  += __shfl_xor_sync(0xffffffffu, s0, o);
                s1  += __shfl_xor_sync(0xffffffffu, s1, o);
                s2v += __shfl_xor_sync(0xffffffffu, s2v, o);
            }
            float p0 = cvalid ? ex2(s0) : 0.f;
            float p1 = cvalid ? ex2(s1) : 0.f;
            float p2 = cvalid ? ex2(s2v) : 0.f;
            den0 += p0; den1 += p1; den2 += p2;
            ac0.x = fmaf(p0, c0.x, ac0.x); ac0.y = fmaf(p0, c0.y, ac0.y);
            ac0.z = fmaf(p0, c0.z, ac0.z); ac0.w = fmaf(p0, c0.w, ac0.w);
            ac1.x = fmaf(p1, c1.x, ac1.x); ac1.y = fmaf(p1, c1.y, ac1.y);
            ac1.z = fmaf(p1, c1.z, ac1.z); ac1.w = fmaf(p1, c1.w, ac1.w);
            ac2.x = fmaf(p2, c2.x, ac2.x); ac2.y = fmaf(p2, c2.y, ac2.y);
            ac2.z = fmaf(p2, c2.z, ac2.z); ac2.w = fmaf(p2, c2.w, ac2.w);
        }
    }

    // cross-group combine (once per node): sum over the 4 groups
#pragma unroll
    for (int o = 8; o <= 16; o <<= 1) {
        den0 += __shfl_xor_sync(0xffffffffu, den0, o);
        den1 += __shfl_xor_sync(0xffffffffu, den1, o);
        den2 += __shfl_xor_sync(0xffffffffu, den2, o);
        ac0.x += __shfl_xor_sync(0xffffffffu, ac0.x, o);
        ac0.y += __shfl_xor_sync(0xffffffffu, ac0.y, o);
        ac0.z += __shfl_xor_sync(0xffffffffu, ac0.z, o);
        ac0.w += __shfl_xor_sync(0xffffffffu, ac0.w, o);
        ac1.x += __shfl_xor_sync(0xffffffffu, ac1.x, o);
        ac1.y += __shfl_xor_sync(0xffffffffu, ac1.y, o);
        ac1.z += __shfl_xor_sync(0xffffffffu, ac1.z, o);
        ac1.w += __shfl_xor_sync(0xffffffffu, ac1.w, o);
        ac2.x += __shfl_xor_sync(0xffffffffu, ac2.x, o);
        ac2.y += __shfl_xor_sync(0xffffffffu, ac2.y, o);
        ac2.z += __shfl_xor_sync(0xffffffffu, ac2.z, o);
        ac2.w += __shfl_xor_sync(0xffffffffu, ac2.w, o);
    }

    if (grp == 0) {
        float r0 = __fdividef(1.f, den0 + 1e-16f);
        float r1 = __fdividef(1.f, den1 + 1e-16f);
        float r2 = __fdividef(1.f, den2 + 1e-16f);
        float4* orow = (float4*)(out + (size_t)v * 96);
        float4 o0 = orow[g], o1 = orow[8 + g], o2 = orow[16 + g];
        o0.x = fmaf(ac0.x, r0, o0.x); o0.y = fmaf(ac0.y, r0, o0.y);
        o0.z = fmaf(ac0.z, r0, o0.z); o0.w = fmaf(ac0.w, r0, o0.w);
        o1.x = fmaf(ac1.x, r1, o1.x); o1.y = fmaf(ac1.y, r1, o1.y);
        o1.z = fmaf(ac1.z, r1, o1.z); o1.w = fmaf(ac1.w, r1, o1.w);
        o2.x = fmaf(ac2.x, r2, o2.x); o2.y = fmaf(ac2.y, r2, o2.y);
        o2.z = fmaf(ac2.z, r2, o2.z); o2.w = fmaf(ac2.w, r2, o2.w);
        orow[g] = o0; orow[8 + g] = o1; orow[16 + g] = o2;
    }
}

// ---------------- launch ------------------------------------------------------

extern "C" void kernel_launch(void* const* d_in, const int* in_sizes, int n_in,
                              void* d_out, int out_size) {
    const float* x     = (const float*)d_in[0];
    const void*  ei    = (const void*)d_in[1];
    const float* W0    = (const float*)d_in[2];
    const float* Wl1   = (const float*)d_in[3];
    const float* bl1   = (const float*)d_in[4];
    const float* Wr1   = (const float*)d_in[5];
    const float* br1   = (const float*)d_in[6];
    const float* att1  = (const float*)d_in[7];
    const float* b1    = (const float*)d_in[8];
    const float* Wf    = (const float*)d_in[9];
    const float* bf    = (const float*)d_in[10];
    const float* Wl2   = (const float*)d_in[11];
    const float* bl2   = (const float*)d_in[12];
    const float* Wr2   = (const float*)d_in[13];
    const float* br2   = (const float*)d_in[14];
    const float* att2  = (const float*)d_in[15];
    const float* b2    = (const float*)d_in[16];
    const float* Wlast = (const float*)d_in[17];
    const float* blast = (const float*)d_in[18];
    float* out = (float*)d_out;

    int n = in_sizes[0] / 128;
    int E = in_sizes[1] / 2;
    int NB = (n + 1023) / 1024;          // scan blocks (<=128)

    k_init<<<(n + 255) / 256, 256>>>((const int*)ei, n);
    k_edges<<<(E + 255) / 256, 256>>>(ei, E);
    k_lin0<<<(n + 15) / 16, 256>>>(x, W0, n);
    k_node1<<<(n + 63) / 64, dim3(96, 4)>>>(Wl1, bl1, Wr1, br1, Wf, bf, b1, n);
    k_scan1<<<NB, 1024>>>(n);
    k_scan2<<<1, 128>>>(NB);
    k_scan3<<<(n + 255) / 256, 256>>>(n, E);
    k_scatter<<<(E + 255) / 256, 256>>>(E);

    // ---- layer 1 edge phase (into g_acc which holds skip + b1) ----
    k_gat<<<(n + 7) / 8, 256>>>(att1, out, 1, n);

    // ---- layer 2 node transforms (relu fused on load; out gets skip + b2) ----
    k_node2<<<(n + 63) / 64, 256>>>(Wl2, bl2, Wr2, br2, Wlast, blast, b2, out, n);

    // ---- layer 2 edge phase (into d_out) ----
    k_gat<<<(n + 7) / 8, 256>>>(att2, out, 0, n);
}